// round 6
// baseline (speedup 1.0000x reference)
#include <cuda_runtime.h>

#define N_NODES 100000
#define N_EDGES 3200000
#define C_DIM   256
#define NEG_SLOPE 0.2f

// Scratch (allocation-free): node score arrays + softmax denominator.
__device__ float g_s_src[N_NODES];
__device__ float g_s_dst[N_NODES];
__device__ float g_denom[N_NODES];

// ---------------------------------------------------------------------------
// Kernel 1: per-node scores s_src = x·att[:C], s_dst = x·att[C:], zero denom.
// Grid-stride warp-per-node with att hoisted to registers ONCE per warp:
// eliminates the 16 L1-hit wavefronts/node the one-shot version paid for
// re-loading att, leaving only the 8 x-wavefronts -> DRAM-bound.
// ---------------------------------------------------------------------------
__global__ void __launch_bounds__(256)
node_scores_kernel(const float* __restrict__ x, const float* __restrict__ att) {
    const int gtid = blockIdx.x * blockDim.x + threadIdx.x;
    const int warp = gtid >> 5;
    const int lane = threadIdx.x & 31;
    const int W    = (gridDim.x * blockDim.x) >> 5;   // total warps

    const float4* a0 = reinterpret_cast<const float4*>(att);          // att[:C]
    const float4* a1 = reinterpret_cast<const float4*>(att + C_DIM);  // att[C:]
    // Hoisted: 8 registers' worth of att per thread, loaded once.
    const float4 av0 = a0[lane],      bv0 = a1[lane];
    const float4 av1 = a0[lane + 32], bv1 = a1[lane + 32];

    for (int node = warp; node < N_NODES; node += W) {
        const float4* xr = reinterpret_cast<const float4*>(x + (size_t)node * C_DIM);
        float4 x0 = __ldcs(&xr[lane]);          // streaming: read-once data
        float4 x1 = __ldcs(&xr[lane + 32]);

        float s0 = x0.x*av0.x + x0.y*av0.y + x0.z*av0.z + x0.w*av0.w
                 + x1.x*av1.x + x1.y*av1.y + x1.z*av1.z + x1.w*av1.w;
        float s1 = x0.x*bv0.x + x0.y*bv0.y + x0.z*bv0.z + x0.w*bv0.w
                 + x1.x*bv1.x + x1.y*bv1.y + x1.z*bv1.z + x1.w*bv1.w;
#pragma unroll
        for (int off = 16; off; off >>= 1) {
            s0 += __shfl_down_sync(0xffffffffu, s0, off);
            s1 += __shfl_down_sync(0xffffffffu, s1, off);
        }
        if (lane == 0) {
            g_s_src[node] = s0;
            g_s_dst[node] = s1;
            g_denom[node] = 0.f;
        }
    }
}

// ---------------------------------------------------------------------------
// Kernel 2: per-edge e = exp(leaky_relu(s_src[row] + s_dst[col])).
// Max-shift dropped (mathematically identical; |a|<=~8, fp32-safe).
// 4 edges/thread, 3125 blocks (measured-best config). Writes e to out,
// RED.ADDs denom[row]. Score tables (800 KB) stay L2-resident.
// ---------------------------------------------------------------------------
__global__ void __launch_bounds__(256)
edge_exp_kernel(const int* __restrict__ row,
                const int* __restrict__ col,
                float* __restrict__ out) {
    int i = blockIdx.x * blockDim.x + threadIdx.x;   // quad index
    if (i * 4 >= N_EDGES) return;

    int4 r4 = __ldcs(&reinterpret_cast<const int4*>(row)[i]);   // read-once
    int4 c4 = __ldcs(&reinterpret_cast<const int4*>(col)[i]);

    // 8 independent scattered gathers in flight
    float ss0 = g_s_src[r4.x], ss1 = g_s_src[r4.y];
    float ss2 = g_s_src[r4.z], ss3 = g_s_src[r4.w];
    float sd0 = g_s_dst[c4.x], sd1 = g_s_dst[c4.y];
    float sd2 = g_s_dst[c4.z], sd3 = g_s_dst[c4.w];

    float a0 = ss0 + sd0, a1 = ss1 + sd1, a2 = ss2 + sd2, a3 = ss3 + sd3;
    a0 = a0 > 0.f ? a0 : NEG_SLOPE * a0;
    a1 = a1 > 0.f ? a1 : NEG_SLOPE * a1;
    a2 = a2 > 0.f ? a2 : NEG_SLOPE * a2;
    a3 = a3 > 0.f ? a3 : NEG_SLOPE * a3;
    float e0 = __expf(a0), e1 = __expf(a1), e2 = __expf(a2), e3 = __expf(a3);

    reinterpret_cast<float4*>(out)[i] = make_float4(e0, e1, e2, e3);

    atomicAdd(&g_denom[r4.x], e0);
    atomicAdd(&g_denom[r4.y], e1);
    atomicAdd(&g_denom[r4.z], e2);
    atomicAdd(&g_denom[r4.w], e3);
}

// ---------------------------------------------------------------------------
// Kernel 3: out[e] = e / denom[row[e]].  2 edges/thread, 6250 blocks
// (measured-best). __fdividef (2^-21 accurate, tol 1e-3) avoids a separate
// reciprocal pass. denom (400 KB) L2-resident, out mostly L2-resident.
// ---------------------------------------------------------------------------
__global__ void __launch_bounds__(256)
normalize_kernel(const int* __restrict__ row, float* __restrict__ out) {
    int i = blockIdx.x * blockDim.x + threadIdx.x;   // pair index
    if (i * 2 >= N_EDGES) return;

    int2 r2 = __ldcs(&reinterpret_cast<const int2*>(row)[i]);

    float d0 = g_denom[r2.x];
    float d1 = g_denom[r2.y];

    float2 v = reinterpret_cast<float2*>(out)[i];
    v.x = __fdividef(v.x, d0);
    v.y = __fdividef(v.y, d1);
    reinterpret_cast<float2*>(out)[i] = v;
}

// ---------------------------------------------------------------------------
extern "C" void kernel_launch(void* const* d_in, const int* in_sizes, int n_in,
                              void* d_out, int out_size) {
    const float* x    = (const float*)d_in[0];   // (N, C) f32
    const float* att  = (const float*)d_in[1];   // (2C, 1) f32
    const int*   edge = (const int*)d_in[2];     // (2, E) int32
    float*       out  = (float*)d_out;           // (1, E) f32

    const int* row = edge;             // edge_index[0]
    const int* col = edge + N_EDGES;   // edge_index[1]

    {   // grid-stride warp-per-node; ~4 waves of 8 warps/block over 100k nodes
        int threads = 256;
        int blocks  = 3200;            // 25600 warps -> ~4 nodes per warp
        node_scores_kernel<<<blocks, threads>>>(x, att);
    }
    {
        int threads = 256;
        int blocks = (N_EDGES / 4 + threads - 1) / threads;
        edge_exp_kernel<<<blocks, threads>>>(row, col, out);
    }
    {
        int threads = 256;
        int blocks = (N_EDGES / 2 + threads - 1) / threads;
        normalize_kernel<<<blocks, threads>>>(row, out);
    }
}

// round 7
// speedup vs baseline: 1.0555x; 1.0555x over previous
#include <cuda_runtime.h>

#define N_NODES 100000
#define N_EDGES 3200000
#define C_DIM   256
#define NEG_SLOPE 0.2f

// Scratch (allocation-free): node score arrays + softmax denominator.
__device__ float g_s_src[N_NODES];
__device__ float g_s_dst[N_NODES];
__device__ float g_denom[N_NODES];

// ---------------------------------------------------------------------------
// Kernel 1: per-node scores s_src = x·att[:C], s_dst = x·att[C:], zero denom.
// One-shot (no loop), TWO nodes per warp: all 4 LDG.128 issued before any
// dependent math (front-batched MLP=4), 4 independent shuffle-reduce chains
// overlap, coalesced float2 stores. N_NODES is even so pairing is exact.
// ---------------------------------------------------------------------------
__global__ void __launch_bounds__(256)
node_scores_kernel(const float* __restrict__ x, const float* __restrict__ att) {
    const int gtid  = blockIdx.x * blockDim.x + threadIdx.x;
    const int warp  = gtid >> 5;            // 0 .. 49999
    const int lane  = threadIdx.x & 31;
    const int nodeA = warp * 2;
    if (nodeA >= N_NODES) return;

    const float4* a0 = reinterpret_cast<const float4*>(att);          // att[:C]
    const float4* a1 = reinterpret_cast<const float4*>(att + C_DIM);  // att[C:]

    // x rows for nodeA and nodeA+1 are contiguous: 4 independent 16B loads.
    const float4* xr = reinterpret_cast<const float4*>(x + (size_t)nodeA * C_DIM);
    float4 xa0 = __ldcs(&xr[lane]);
    float4 xa1 = __ldcs(&xr[lane + 32]);
    float4 xb0 = __ldcs(&xr[lane + 64]);
    float4 xb1 = __ldcs(&xr[lane + 96]);

    float4 av0 = a0[lane],      bv0 = a1[lane];       // L1/L2-resident (2KB)
    float4 av1 = a0[lane + 32], bv1 = a1[lane + 32];

    float s0a = xa0.x*av0.x + xa0.y*av0.y + xa0.z*av0.z + xa0.w*av0.w
              + xa1.x*av1.x + xa1.y*av1.y + xa1.z*av1.z + xa1.w*av1.w;
    float s1a = xa0.x*bv0.x + xa0.y*bv0.y + xa0.z*bv0.z + xa0.w*bv0.w
              + xa1.x*bv1.x + xa1.y*bv1.y + xa1.z*bv1.z + xa1.w*bv1.w;
    float s0b = xb0.x*av0.x + xb0.y*av0.y + xb0.z*av0.z + xb0.w*av0.w
              + xb1.x*av1.x + xb1.y*av1.y + xb1.z*av1.z + xb1.w*av1.w;
    float s1b = xb0.x*bv0.x + xb0.y*bv0.y + xb0.z*bv0.z + xb0.w*bv0.w
              + xb1.x*bv1.x + xb1.y*bv1.y + xb1.z*bv1.z + xb1.w*bv1.w;

#pragma unroll
    for (int off = 16; off; off >>= 1) {   // 4 independent reduce chains
        s0a += __shfl_down_sync(0xffffffffu, s0a, off);
        s1a += __shfl_down_sync(0xffffffffu, s1a, off);
        s0b += __shfl_down_sync(0xffffffffu, s0b, off);
        s1b += __shfl_down_sync(0xffffffffu, s1b, off);
    }
    if (lane == 0) {   // coalesced pair stores (nodeA even -> 8B aligned)
        *reinterpret_cast<float2*>(&g_s_src[nodeA]) = make_float2(s0a, s0b);
        *reinterpret_cast<float2*>(&g_s_dst[nodeA]) = make_float2(s1a, s1b);
        *reinterpret_cast<float2*>(&g_denom[nodeA]) = make_float2(0.f, 0.f);
    }
}

// ---------------------------------------------------------------------------
// Kernel 2: per-edge e = exp(leaky_relu(s_src[row] + s_dst[col])).
// Max-shift dropped (mathematically identical; |a|<=~8, fp32-safe).
// 4 edges/thread, 3125 blocks (measured-best). row uses DEFAULT caching so it
// stays L2-resident for normalize's re-read; col is genuinely read-once.
// ---------------------------------------------------------------------------
__global__ void __launch_bounds__(256)
edge_exp_kernel(const int* __restrict__ row,
                const int* __restrict__ col,
                float* __restrict__ out) {
    int i = blockIdx.x * blockDim.x + threadIdx.x;   // quad index
    if (i * 4 >= N_EDGES) return;

    int4 r4 = reinterpret_cast<const int4*>(row)[i];            // keep in L2
    int4 c4 = __ldcs(&reinterpret_cast<const int4*>(col)[i]);   // read-once

    // 8 independent scattered gathers in flight
    float ss0 = g_s_src[r4.x], ss1 = g_s_src[r4.y];
    float ss2 = g_s_src[r4.z], ss3 = g_s_src[r4.w];
    float sd0 = g_s_dst[c4.x], sd1 = g_s_dst[c4.y];
    float sd2 = g_s_dst[c4.z], sd3 = g_s_dst[c4.w];

    float a0 = ss0 + sd0, a1 = ss1 + sd1, a2 = ss2 + sd2, a3 = ss3 + sd3;
    a0 = a0 > 0.f ? a0 : NEG_SLOPE * a0;
    a1 = a1 > 0.f ? a1 : NEG_SLOPE * a1;
    a2 = a2 > 0.f ? a2 : NEG_SLOPE * a2;
    a3 = a3 > 0.f ? a3 : NEG_SLOPE * a3;
    float e0 = __expf(a0), e1 = __expf(a1), e2 = __expf(a2), e3 = __expf(a3);

    reinterpret_cast<float4*>(out)[i] = make_float4(e0, e1, e2, e3);

    atomicAdd(&g_denom[r4.x], e0);
    atomicAdd(&g_denom[r4.y], e1);
    atomicAdd(&g_denom[r4.z], e2);
    atomicAdd(&g_denom[r4.w], e3);
}

// ---------------------------------------------------------------------------
// Kernel 3: out[e] = e / denom[row[e]].  2 edges/thread, 6250 blocks
// (measured-best). row + out should hit L2 (row kept resident by kernel 2,
// out written there). __fdividef (2^-21, tol 1e-3) avoids a reciprocal pass.
// ---------------------------------------------------------------------------
__global__ void __launch_bounds__(256)
normalize_kernel(const int* __restrict__ row, float* __restrict__ out) {
    int i = blockIdx.x * blockDim.x + threadIdx.x;   // pair index
    if (i * 2 >= N_EDGES) return;

    int2 r2 = reinterpret_cast<const int2*>(row)[i];   // L2 hit expected

    float d0 = g_denom[r2.x];
    float d1 = g_denom[r2.y];

    float2 v = reinterpret_cast<float2*>(out)[i];
    v.x = __fdividef(v.x, d0);
    v.y = __fdividef(v.y, d1);
    reinterpret_cast<float2*>(out)[i] = v;
}

// ---------------------------------------------------------------------------
extern "C" void kernel_launch(void* const* d_in, const int* in_sizes, int n_in,
                              void* d_out, int out_size) {
    const float* x    = (const float*)d_in[0];   // (N, C) f32
    const float* att  = (const float*)d_in[1];   // (2C, 1) f32
    const int*   edge = (const int*)d_in[2];     // (2, E) int32
    float*       out  = (float*)d_out;           // (1, E) f32

    const int* row = edge;             // edge_index[0]
    const int* col = edge + N_EDGES;   // edge_index[1]

    {   // one-shot, 2 nodes per warp: 50000 warps = 6250 blocks
        int threads = 256;
        int blocks  = (N_NODES / 2 * 32) / threads;   // 6250
        node_scores_kernel<<<blocks, threads>>>(x, att);
    }
    {
        int threads = 256;
        int blocks = (N_EDGES / 4 + threads - 1) / threads;
        edge_exp_kernel<<<blocks, threads>>>(row, col, out);
    }
    {
        int threads = 256;
        int blocks = (N_EDGES / 2 + threads - 1) / threads;
        normalize_kernel<<<blocks, threads>>>(row, out);
    }
}